// round 7
// baseline (speedup 1.0000x reference)
#include <cuda_runtime.h>
#include <cuda_fp16.h>
#include <cstdint>

// Problem shape (fixed per metadata):
//   X0 [4,1024,256] f32, t [4,1] f32, Wc_w [128,256] f32, Wc_b [128] f32,
//   w [128] f32, A [64,128,6] f32, Bp [64,128,6] f32  ->  out [4,1024,64] f32
#define B_   4
#define S_   1024
#define ROWS 4096        // B_*S_
#define DIN  256
#define Q_   128
#define KF   6
#define DOUT 64
#define KSL  1536        // GEMM2: 1 fp16 slot per feature
#define WPL  512         // GEMM1 B: 2 planes (wh | wl) of 256 slots

// Scratch (no device allocs allowed)
__device__ __half g_bh[DOUT * KSL];            // 192 KB  [d][k] fp16 coeffs
__device__ __half g_wsp[Q_ * WPL];             // 128 KB  [q][wh(256)|wl(256)]

// ---------------------------------------------------------------------------
// m16n8k16 fp16 MMA, fp32 accumulate
// ---------------------------------------------------------------------------
__device__ __forceinline__ void mma16816(float* c, const uint32_t* a,
                                         const uint32_t* b) {
    asm volatile(
        "mma.sync.aligned.m16n8k16.row.col.f32.f16.f16.f32 "
        "{%0,%1,%2,%3}, {%4,%5,%6,%7}, {%8,%9}, {%0,%1,%2,%3};"
        : "+f"(c[0]), "+f"(c[1]), "+f"(c[2]), "+f"(c[3])
        : "r"(a[0]), "r"(a[1]), "r"(a[2]), "r"(a[3]), "r"(b[0]), "r"(b[1]));
}

// ---------------------------------------------------------------------------
// Kernel 1 (prep): fold A,Bp -> g_bh; split W -> wh/wl planes. x2 vectorized,
// all stores coalesced (uint2 / uint32).
// ---------------------------------------------------------------------------
__global__ void prep_kernel(const float* __restrict__ A, const float* __restrict__ Bp,
                            const float* __restrict__ W) {
    int i = blockIdx.x * blockDim.x + threadIdx.x;       // 0 .. 24575
    {   // g_bh: items 2i, 2i+1  (49152 total)
        int idx = 2 * i;
        int d   = idx / (Q_ * KF);
        int rem = idx - d * (Q_ * KF);                   // even
        float2 a2 = *(const float2*)&A[idx];
        float2 b2 = *(const float2*)&Bp[idx];
        float s0, c0, s1, c1;
        __sincosf(b2.x, &s0, &c0);
        __sincosf(b2.y, &s1, &c1);
        __half2 h0 = __floats2half2_rn(a2.x * c0, a2.x * s0);
        __half2 h1 = __floats2half2_rn(a2.y * c1, a2.y * s1);
        *(uint2*)&g_bh[d * KSL + rem * 2] =
            make_uint2(*(uint32_t*)&h0, *(uint32_t*)&h1);
    }
    if (i < (Q_ * DIN) / 2) {                            // W: items 2i, 2i+1
        int idx = 2 * i;
        int q = idx >> 8, k = idx & 255;                 // k even
        float2 w2 = *(const float2*)&W[idx];
        __half wh0 = __float2half_rn(w2.x);
        __half wl0 = __float2half_rn(w2.x - __half2float(wh0));
        __half wh1 = __float2half_rn(w2.y);
        __half wl1 = __float2half_rn(w2.y - __half2float(wh1));
        __half2 hp = __halves2half2(wh0, wh1);
        __half2 lp = __halves2half2(wl0, wl1);
        *(uint32_t*)&g_wsp[q * WPL + k]       = *(uint32_t*)&hp;
        *(uint32_t*)&g_wsp[q * WPL + 256 + k] = *(uint32_t*)&lp;
    }
}

// ---------------------------------------------------------------------------
// Kernel 2 (mega): GEMM1 (angle) -> smem -> featgen -> GEMM2, one CTA pass.
// 128 CTAs x 128 threads, 32 rows each. Static smem, phase-unioned:
//   [0,16896)      ANG   : angle tile f32 [q][33]            (phase1->phase2)
//   [16896,23552)  As2   : phase-2 A  [32][104] halves   }  overlaps phase-1
//   [23552,36864)  Bs2   : phase-2 B  [64][104] halves   }  Ws [128][72]
//   [36864,41472)  Ax1   : phase-1 A  [32][72]  halves
// Phase 1: K=256 f32, 8 chunks of 32. A slots [xh|xl], B slots [wh|wl];
//          3 products xh*wh + xh*wl + xl*wh (xl*wl dropped, <=2^-22 rel).
// Phase 2: K=1536, 16 chunks of 8 q (96 slots, 6 ktiles).
// ---------------------------------------------------------------------------
#define KP1 72
#define KP2 104
#define SM_BYTES 41472

__global__ __launch_bounds__(128) void mega_kernel(
    const float* __restrict__ X0, const float* __restrict__ bias,
    const float* __restrict__ wvec, const float* __restrict__ tvec,
    float* __restrict__ out)
{
    __shared__ __align__(16) char sm[SM_BYTES];
    float*  ANG = (float*)sm;                       // [q*33 + row]
    __half* As2 = (__half*)(sm + 16896);            // [row][KP2]
    __half* Bs2 = (__half*)(sm + 23552);            // [d][KP2]
    __half* Ws1 = (__half*)(sm + 16896);            // [q][KP1]
    __half* Ax1 = (__half*)(sm + 36864);            // [row][KP1]

    int tid  = threadIdx.x;
    int lane = tid & 31;
    int w    = tid >> 5;
    int r0   = blockIdx.x * 32;
    int ra   = lane >> 2;
    int cc   = 2 * (lane & 3);

    // ======================= PHASE 1: angle GEMM =======================
    {
        float acc[2][4][4] = {};          // [mtile][ntile][frag]
        int xrow = tid >> 2;              // 0..31
        int kgrp = (tid & 3) * 8;         // f32 k offset within chunk

        // prologue prefetch chunk 0: q = tid, full 32 wh + 32 wl halves
        float4 nx0 = *(const float4*)&X0[(r0 + xrow) * DIN + kgrp];
        float4 nx1 = *(const float4*)&X0[(r0 + xrow) * DIN + kgrp + 4];
        uint4 nW[8];
        #pragma unroll
        for (int j = 0; j < 4; j++) {
            nW[j]     = *(const uint4*)&g_wsp[tid * WPL + j * 8];
            nW[4 + j] = *(const uint4*)&g_wsp[tid * WPL + 256 + j * 8];
        }

        for (int c = 0; c < 8; c++) {
            // ---- stage A: split 8 f32 -> xh(8) cols kgrp, xl(8) cols 32+kgrp
            {
                float xf[8] = {nx0.x, nx0.y, nx0.z, nx0.w,
                               nx1.x, nx1.y, nx1.z, nx1.w};
                uint32_t ph[4], pl[4];
                #pragma unroll
                for (int j = 0; j < 4; j++) {
                    float a0 = xf[2 * j], a1 = xf[2 * j + 1];
                    __half h0 = __float2half_rn(a0);
                    __half l0 = __float2half_rn(a0 - __half2float(h0));
                    __half h1 = __float2half_rn(a1);
                    __half l1 = __float2half_rn(a1 - __half2float(h1));
                    __half2 hh = __halves2half2(h0, h1);
                    __half2 ll = __halves2half2(l0, l1);
                    ph[j] = *(uint32_t*)&hh;
                    pl[j] = *(uint32_t*)&ll;
                }
                *(uint4*)&Ax1[xrow * KP1 + kgrp]      = make_uint4(ph[0], ph[1], ph[2], ph[3]);
                *(uint4*)&Ax1[xrow * KP1 + 32 + kgrp] = make_uint4(pl[0], pl[1], pl[2], pl[3]);
            }
            // ---- stage B: wh cols 0-31, wl cols 32-63 (q = tid) ----
            #pragma unroll
            for (int j = 0; j < 4; j++) {
                *(uint4*)&Ws1[tid * KP1 + j * 8]      = nW[j];
                *(uint4*)&Ws1[tid * KP1 + 32 + j * 8] = nW[4 + j];
            }
            __syncthreads();

            // ---- prefetch next chunk (hidden under MMA) ----
            if (c < 7) {
                nx0 = *(const float4*)&X0[(r0 + xrow) * DIN + (c + 1) * 32 + kgrp];
                nx1 = *(const float4*)&X0[(r0 + xrow) * DIN + (c + 1) * 32 + kgrp + 4];
                #pragma unroll
                for (int j = 0; j < 4; j++) {
                    nW[j]     = *(const uint4*)&g_wsp[tid * WPL + (c + 1) * 32 + j * 8];
                    nW[4 + j] = *(const uint4*)&g_wsp[tid * WPL + 256 + (c + 1) * 32 + j * 8];
                }
            }

            // ---- MMA: 2 ktiles x {xh*wh, xh*wl, xl*wh} x 2m x 4n ----
            #pragma unroll
            for (int kt = 0; kt < 2; kt++) {
                int kh = kt * 16 + cc;        // xh / wh cols
                int kl = 32 + kh;             // xl / wl cols
                uint32_t A0h[4], A1h[4], A0l[4], A1l[4];
                A0h[0] = *(const uint32_t*)&Ax1[ra * KP1 + kh];
                A0h[1] = *(const uint32_t*)&Ax1[(ra + 8) * KP1 + kh];
                A0h[2] = *(const uint32_t*)&Ax1[ra * KP1 + kh + 8];
                A0h[3] = *(const uint32_t*)&Ax1[(ra + 8) * KP1 + kh + 8];
                A1h[0] = *(const uint32_t*)&Ax1[(ra + 16) * KP1 + kh];
                A1h[1] = *(const uint32_t*)&Ax1[(ra + 24) * KP1 + kh];
                A1h[2] = *(const uint32_t*)&Ax1[(ra + 16) * KP1 + kh + 8];
                A1h[3] = *(const uint32_t*)&Ax1[(ra + 24) * KP1 + kh + 8];
                A0l[0] = *(const uint32_t*)&Ax1[ra * KP1 + kl];
                A0l[1] = *(const uint32_t*)&Ax1[(ra + 8) * KP1 + kl];
                A0l[2] = *(const uint32_t*)&Ax1[ra * KP1 + kl + 8];
                A0l[3] = *(const uint32_t*)&Ax1[(ra + 8) * KP1 + kl + 8];
                A1l[0] = *(const uint32_t*)&Ax1[(ra + 16) * KP1 + kl];
                A1l[1] = *(const uint32_t*)&Ax1[(ra + 24) * KP1 + kl];
                A1l[2] = *(const uint32_t*)&Ax1[(ra + 16) * KP1 + kl + 8];
                A1l[3] = *(const uint32_t*)&Ax1[(ra + 24) * KP1 + kl + 8];
                #pragma unroll
                for (int n = 0; n < 4; n++) {
                    int q0 = w * 32 + n * 8 + ra;
                    uint32_t Bh[2], Bl[2];
                    Bh[0] = *(const uint32_t*)&Ws1[q0 * KP1 + kh];
                    Bh[1] = *(const uint32_t*)&Ws1[q0 * KP1 + kh + 8];
                    Bl[0] = *(const uint32_t*)&Ws1[q0 * KP1 + kl];
                    Bl[1] = *(const uint32_t*)&Ws1[q0 * KP1 + kl + 8];
                    mma16816(acc[0][n], A0h, Bh);   // xh*wh
                    mma16816(acc[1][n], A1h, Bh);
                    mma16816(acc[0][n], A0h, Bl);   // xh*wl
                    mma16816(acc[1][n], A1h, Bl);
                    mma16816(acc[0][n], A0l, Bh);   // xl*wh
                    mma16816(acc[1][n], A1l, Bh);
                }
            }
            __syncthreads();
        }

        // ---- epilogue: + bias + w*t -> ANG smem [q][33] ----
        float tb = tvec[r0 >> 10];
        #pragma unroll
        for (int n = 0; n < 4; n++) {
            int q = w * 32 + n * 8 + cc;
            float b0 = __ldg(&bias[q])     + __ldg(&wvec[q]) * tb;
            float b1 = __ldg(&bias[q + 1]) + __ldg(&wvec[q + 1]) * tb;
            #pragma unroll
            for (int m = 0; m < 2; m++) {
                int rr = m * 16 + ra;
                float* a4 = acc[m][n];
                ANG[q * 33 + rr]           = a4[0] + b0;
                ANG[(q + 1) * 33 + rr]     = a4[1] + b1;
                ANG[q * 33 + rr + 8]       = a4[2] + b0;
                ANG[(q + 1) * 33 + rr + 8] = a4[3] + b1;
            }
        }
    }
    __syncthreads();

    // ================= PHASE 2: featgen + GEMM2 =================
    {
        float acc[2][2][4] = {};
        int row = lane;                   // featgen row
        // featgen q-pair: local q = 2w, 2w+1

        // prologue prefetch B chunk 0 (6 uint4 / thread: 64 d x 12 uint4)
        uint4 nB[6];
        #pragma unroll
        for (int r = 0; r < 6; r++) {
            int idx = tid + 128 * r;      // 0..767
            int d   = idx / 12;
            int kc  = idx - d * 12;
            nB[r] = *(const uint4*)&g_bh[d * KSL + kc * 8];
        }

        for (int c = 0; c < 16; c++) {
            // ---- features for 2 q's -> fp16 -> As2 ----
            #pragma unroll
            for (int p = 0; p < 2; p++) {
                int ql = 2 * w + p;
                float a = ANG[(c * 8 + ql) * 33 + row];
                // Cody-Waite reduction mod 2*pi (C1=6.28125: 9 mantissa bits)
                float n = rintf(a * 0.15915494309189535f);
                float rr = fmaf(n, -6.28125f, a);
                rr = fmaf(n, -1.9353071795864769e-3f, rr);
                float s1, c1;
                __sincosf(rr, &s1, &c1);
                float f[12];
                f[0] = s1; f[1] = c1;
                float sk = s1, ck = c1;
                #pragma unroll
                for (int h = 1; h < KF; h++) {
                    float sn = fmaf(sk, c1, ck * s1);
                    float cn = fmaf(ck, c1, -sk * s1);
                    f[2 * h] = sn; f[2 * h + 1] = cn;
                    sk = sn; ck = cn;
                }
                uint32_t hv[6];
                #pragma unroll
                for (int g = 0; g < 6; g++) {
                    __half2 h2 = __floats2half2_rn(f[2 * g], f[2 * g + 1]);
                    hv[g] = *(uint32_t*)&h2;
                }
                uint64_t* dst = (uint64_t*)&As2[row * KP2 + ql * 12];
                dst[0] = (uint64_t)hv[0] | ((uint64_t)hv[1] << 32);
                dst[1] = (uint64_t)hv[2] | ((uint64_t)hv[3] << 32);
                dst[2] = (uint64_t)hv[4] | ((uint64_t)hv[5] << 32);
            }
            // ---- stage B chunk (full 96 cols) ----
            #pragma unroll
            for (int r = 0; r < 6; r++) {
                int idx = tid + 128 * r;
                int d   = idx / 12;
                int kc  = idx - d * 12;
                *(uint4*)&Bs2[d * KP2 + kc * 8] = nB[r];
            }
            __syncthreads();

            // ---- prefetch next B chunk ----
            if (c < 15) {
                #pragma unroll
                for (int r = 0; r < 6; r++) {
                    int idx = tid + 128 * r;
                    int d   = idx / 12;
                    int kc  = idx - d * 12;
                    nB[r] = *(const uint4*)&g_bh[d * KSL + (c + 1) * 96 + kc * 8];
                }
            }

            // ---- MMA: 6 ktiles x (2m x 2n) ----
            #pragma unroll
            for (int kt = 0; kt < 6; kt++) {
                int k0 = kt * 16 + cc;
                uint32_t A0[4], A1[4], Bf0[2], Bf1[2];
                A0[0] = *(const uint32_t*)&As2[ra * KP2 + k0];
                A0[1] = *(const uint32_t*)&As2[(ra + 8) * KP2 + k0];
                A0[2] = *(const uint32_t*)&As2[ra * KP2 + k0 + 8];
                A0[3] = *(const uint32_t*)&As2[(ra + 8) * KP2 + k0 + 8];
                A1[0] = *(const uint32_t*)&As2[(ra + 16) * KP2 + k0];
                A1[1] = *(const uint32_t*)&As2[(ra + 24) * KP2 + k0];
                A1[2] = *(const uint32_t*)&As2[(ra + 16) * KP2 + k0 + 8];
                A1[3] = *(const uint32_t*)&As2[(ra + 24) * KP2 + k0 + 8];
                int d0 = w * 16 + ra;
                Bf0[0] = *(const uint32_t*)&Bs2[d0 * KP2 + k0];
                Bf0[1] = *(const uint32_t*)&Bs2[d0 * KP2 + k0 + 8];
                Bf1[0] = *(const uint32_t*)&Bs2[(d0 + 8) * KP2 + k0];
                Bf1[1] = *(const uint32_t*)&Bs2[(d0 + 8) * KP2 + k0 + 8];
                mma16816(acc[0][0], A0, Bf0);
                mma16816(acc[0][1], A0, Bf1);
                mma16816(acc[1][0], A1, Bf0);
                mma16816(acc[1][1], A1, Bf1);
            }
            __syncthreads();
        }

        // ---- output epilogue ----
        int orow = r0 + ra;
        int ocol = w * 16 + cc;
        #pragma unroll
        for (int m = 0; m < 2; m++) {
            #pragma unroll
            for (int nt = 0; nt < 2; nt++) {
                float* a4 = acc[m][nt];
                int rr  = orow + m * 16;
                int ccg = ocol + nt * 8;
                *(float2*)&out[rr * DOUT + ccg]       = make_float2(a4[0], a4[1]);
                *(float2*)&out[(rr + 8) * DOUT + ccg] = make_float2(a4[2], a4[3]);
            }
        }
    }
}

// ---------------------------------------------------------------------------
extern "C" void kernel_launch(void* const* d_in, const int* in_sizes, int n_in,
                              void* d_out, int out_size) {
    const float* X0   = (const float*)d_in[0];
    const float* tvec = (const float*)d_in[1];
    const float* Wc_w = (const float*)d_in[2];
    const float* Wc_b = (const float*)d_in[3];
    const float* wvec = (const float*)d_in[4];
    const float* A    = (const float*)d_in[5];
    const float* Bp   = (const float*)d_in[6];
    float* out = (float*)d_out;

    prep_kernel<<<96, 256>>>(A, Bp, Wc_w);
    mega_kernel<<<ROWS / 32, 128>>>(X0, Wc_b, wvec, tvec, out);
}

// round 8
// speedup vs baseline: 1.0012x; 1.0012x over previous
#include <cuda_runtime.h>
#include <cuda_fp16.h>
#include <cstdint>

// Problem shape (fixed per metadata):
//   X0 [4,1024,256] f32, t [4,1] f32, Wc_w [128,256] f32, Wc_b [128] f32,
//   w [128] f32, A [64,128,6] f32, Bp [64,128,6] f32  ->  out [4,1024,64] f32
#define B_   4
#define S_   1024
#define ROWS 4096        // B_*S_
#define DIN  256
#define Q_   128
#define KF   6
#define DOUT 64
#define KSL  1536        // GEMM2: 1 fp16 slot per feature
#define WPL  512         // GEMM1 B: 2 planes (wh | wl) of 256 slots

// Scratch (no device allocs allowed)
__device__ __half g_bh[DOUT * KSL];            // 192 KB  [d][k] fp16 coeffs
__device__ __half g_wsp[Q_ * WPL];             // 128 KB  [q][wh(256)|wl(256)]

// ---------------------------------------------------------------------------
// m16n8k16 fp16 MMA, fp32 accumulate
// ---------------------------------------------------------------------------
__device__ __forceinline__ void mma16816(float* c, const uint32_t* a,
                                         const uint32_t* b) {
    asm volatile(
        "mma.sync.aligned.m16n8k16.row.col.f32.f16.f16.f32 "
        "{%0,%1,%2,%3}, {%4,%5,%6,%7}, {%8,%9}, {%0,%1,%2,%3};"
        : "+f"(c[0]), "+f"(c[1]), "+f"(c[2]), "+f"(c[3])
        : "r"(a[0]), "r"(a[1]), "r"(a[2]), "r"(a[3]), "r"(b[0]), "r"(b[1]));
}

// ---------------------------------------------------------------------------
// Kernel 1 (prep): fold A,Bp -> g_bh; split W -> wh/wl planes.
// ---------------------------------------------------------------------------
__global__ void prep_kernel(const float* __restrict__ A, const float* __restrict__ Bp,
                            const float* __restrict__ W) {
    int i = blockIdx.x * blockDim.x + threadIdx.x;       // 0 .. 24575
    {   // g_bh: items 2i, 2i+1  (49152 total)
        int idx = 2 * i;
        int d   = idx / (Q_ * KF);
        int rem = idx - d * (Q_ * KF);                   // even
        float2 a2 = *(const float2*)&A[idx];
        float2 b2 = *(const float2*)&Bp[idx];
        float s0, c0, s1, c1;
        __sincosf(b2.x, &s0, &c0);
        __sincosf(b2.y, &s1, &c1);
        __half2 h0 = __floats2half2_rn(a2.x * c0, a2.x * s0);
        __half2 h1 = __floats2half2_rn(a2.y * c1, a2.y * s1);
        *(uint2*)&g_bh[d * KSL + rem * 2] =
            make_uint2(*(uint32_t*)&h0, *(uint32_t*)&h1);
    }
    if (i < (Q_ * DIN) / 2) {                            // W: items 2i, 2i+1
        int idx = 2 * i;
        int q = idx >> 8, k = idx & 255;                 // k even
        float2 w2 = *(const float2*)&W[idx];
        __half wh0 = __float2half_rn(w2.x);
        __half wl0 = __float2half_rn(w2.x - __half2float(wh0));
        __half wh1 = __float2half_rn(w2.y);
        __half wl1 = __float2half_rn(w2.y - __half2float(wh1));
        __half2 hp = __halves2half2(wh0, wh1);
        __half2 lp = __halves2half2(wl0, wl1);
        *(uint32_t*)&g_wsp[q * WPL + k]       = *(uint32_t*)&hp;
        *(uint32_t*)&g_wsp[q * WPL + 256 + k] = *(uint32_t*)&lp;
    }
}

// ---------------------------------------------------------------------------
// Kernel 2 (mega): GEMM1 -> smem -> featgen -> GEMM2. 128 CTAs x 256 threads
// (8 warps: 2 row-groups x 4 col-groups), 32 rows per CTA.
// Static smem, phase-unioned:
//   [0,16896)      ANG : angle tile f32 [q][33]
//   [16896,23552)  As2 : phase-2 A [32][104] halves  }  overlaps phase-1
//   [23552,36864)  Bs2 : phase-2 B [64][104] halves  }  Ws1 [128][72]
//   [36864,41472)  Ax1 : phase-1 A [32][72] halves
// Phase 1: K=256 f32, 8 chunks of 32 -> 64 slots [xh|xl]; products
//          xh*wh + xh*wl + xl*wh (xl*wl dropped, <=2^-22 rel).
// Phase 2: K=1536, 16 chunks of 8 q (96 slots, 6 ktiles).
// ---------------------------------------------------------------------------
#define KP1 72
#define KP2 104
#define SM_BYTES 41472

__global__ __launch_bounds__(256) void mega_kernel(
    const float* __restrict__ X0, const float* __restrict__ bias,
    const float* __restrict__ wvec, const float* __restrict__ tvec,
    float* __restrict__ out)
{
    __shared__ __align__(16) char sm[SM_BYTES];
    float*  ANG = (float*)sm;                       // [q*33 + row]
    __half* As2 = (__half*)(sm + 16896);            // [row][KP2]
    __half* Bs2 = (__half*)(sm + 23552);            // [d][KP2]
    __half* Ws1 = (__half*)(sm + 16896);            // [q][KP1]
    __half* Ax1 = (__half*)(sm + 36864);            // [row][KP1]

    int tid  = threadIdx.x;
    int lane = tid & 31;
    int w    = tid >> 5;              // warp 0..7
    int r0   = blockIdx.x * 32;
    int ra   = lane >> 2;
    int cc   = 2 * (lane & 3);

    // ======================= PHASE 1: angle GEMM =======================
    {
        int wr = w >> 2;              // row group: rows wr*16 .. wr*16+15
        int wq = w & 3;               // q group:   q wq*32 .. wq*32+31
        float acc[4][4] = {};         // [ntile][frag]

        int xrow = tid >> 3;          // 0..31 (A staging row)
        int kgrp = (tid & 7) * 4;     // f32 k offset within chunk (4 floats)
        int qW   = tid >> 1;          // 0..127 (B staging q)
        int jj   = (tid & 1) * 2;     // uint4 pair within q

        // prologue prefetch chunk 0
        float4 nx = *(const float4*)&X0[(r0 + xrow) * DIN + kgrp];
        uint4 nW[4];
        #pragma unroll
        for (int j = 0; j < 2; j++) {
            nW[j]     = *(const uint4*)&g_wsp[qW * WPL + (jj + j) * 8];
            nW[2 + j] = *(const uint4*)&g_wsp[qW * WPL + 256 + (jj + j) * 8];
        }

        for (int c = 0; c < 8; c++) {
            // ---- stage A: split 4 f32 -> xh at col kgrp, xl at col 32+kgrp
            {
                float xf[4] = {nx.x, nx.y, nx.z, nx.w};
                uint32_t ph[2], pl[2];
                #pragma unroll
                for (int j = 0; j < 2; j++) {
                    float a0 = xf[2 * j], a1 = xf[2 * j + 1];
                    __half h0 = __float2half_rn(a0);
                    __half l0 = __float2half_rn(a0 - __half2float(h0));
                    __half h1 = __float2half_rn(a1);
                    __half l1 = __float2half_rn(a1 - __half2float(h1));
                    __half2 hh = __halves2half2(h0, h1);
                    __half2 ll = __halves2half2(l0, l1);
                    ph[j] = *(uint32_t*)&hh;
                    pl[j] = *(uint32_t*)&ll;
                }
                *(uint2*)&Ax1[xrow * KP1 + kgrp]      = make_uint2(ph[0], ph[1]);
                *(uint2*)&Ax1[xrow * KP1 + 32 + kgrp] = make_uint2(pl[0], pl[1]);
            }
            // ---- stage B: wh cols 0-31, wl cols 32-63 ----
            #pragma unroll
            for (int j = 0; j < 2; j++) {
                *(uint4*)&Ws1[qW * KP1 + (jj + j) * 8]      = nW[j];
                *(uint4*)&Ws1[qW * KP1 + 32 + (jj + j) * 8] = nW[2 + j];
            }
            __syncthreads();

            // ---- prefetch next chunk (hidden under MMA) ----
            if (c < 7) {
                nx = *(const float4*)&X0[(r0 + xrow) * DIN + (c + 1) * 32 + kgrp];
                #pragma unroll
                for (int j = 0; j < 2; j++) {
                    nW[j]     = *(const uint4*)&g_wsp[qW * WPL + (c + 1) * 32 + (jj + j) * 8];
                    nW[2 + j] = *(const uint4*)&g_wsp[qW * WPL + 256 + (c + 1) * 32 + (jj + j) * 8];
                }
            }

            // ---- MMA: 2 ktiles x {xh*wh, xh*wl, xl*wh} x 4n ----
            #pragma unroll
            for (int kt = 0; kt < 2; kt++) {
                int kh = kt * 16 + cc;        // xh / wh cols
                int kl = 32 + kh;             // xl / wl cols
                int mr = wr * 16 + ra;
                uint32_t Ah[4], Al[4];
                Ah[0] = *(const uint32_t*)&Ax1[mr * KP1 + kh];
                Ah[1] = *(const uint32_t*)&Ax1[(mr + 8) * KP1 + kh];
                Ah[2] = *(const uint32_t*)&Ax1[mr * KP1 + kh + 8];
                Ah[3] = *(const uint32_t*)&Ax1[(mr + 8) * KP1 + kh + 8];
                Al[0] = *(const uint32_t*)&Ax1[mr * KP1 + kl];
                Al[1] = *(const uint32_t*)&Ax1[(mr + 8) * KP1 + kl];
                Al[2] = *(const uint32_t*)&Ax1[mr * KP1 + kl + 8];
                Al[3] = *(const uint32_t*)&Ax1[(mr + 8) * KP1 + kl + 8];
                #pragma unroll
                for (int n = 0; n < 4; n++) {
                    int q0 = wq * 32 + n * 8 + ra;
                    uint32_t Bh[2], Bl[2];
                    Bh[0] = *(const uint32_t*)&Ws1[q0 * KP1 + kh];
                    Bh[1] = *(const uint32_t*)&Ws1[q0 * KP1 + kh + 8];
                    Bl[0] = *(const uint32_t*)&Ws1[q0 * KP1 + kl];
                    Bl[1] = *(const uint32_t*)&Ws1[q0 * KP1 + kl + 8];
                    mma16816(acc[n], Ah, Bh);   // xh*wh
                    mma16816(acc[n], Ah, Bl);   // xh*wl
                    mma16816(acc[n], Al, Bh);   // xl*wh
                }
            }
            __syncthreads();
        }

        // ---- epilogue: + bias + w*t -> ANG smem [q][33] ----
        float tb = tvec[r0 >> 10];
        #pragma unroll
        for (int n = 0; n < 4; n++) {
            int q  = wq * 32 + n * 8 + cc;
            int rr = wr * 16 + ra;
            float b0 = __ldg(&bias[q])     + __ldg(&wvec[q]) * tb;
            float b1 = __ldg(&bias[q + 1]) + __ldg(&wvec[q + 1]) * tb;
            ANG[q * 33 + rr]           = acc[n][0] + b0;
            ANG[(q + 1) * 33 + rr]     = acc[n][1] + b1;
            ANG[q * 33 + rr + 8]       = acc[n][2] + b0;
            ANG[(q + 1) * 33 + rr + 8] = acc[n][3] + b1;
        }
    }
    __syncthreads();

    // ================= PHASE 2: featgen + GEMM2 =================
    {
        int wr2 = w >> 2;             // row group: rows wr2*16 ..
        int wd  = w & 3;              // d group:   d wd*16 .. wd*16+15
        float acc[2][4] = {};         // [ntile][frag]

        int row = tid & 31;           // featgen row
        int ql  = tid >> 5;           // featgen local q (0..7), 1 per thread

        // prologue prefetch B chunk 0 (3 uint4 / thread: 64 d x 12 uint4)
        uint4 nB[3];
        #pragma unroll
        for (int r = 0; r < 3; r++) {
            int idx = tid + 256 * r;  // 0..767
            int d   = idx / 12;
            int kc  = idx - d * 12;
            nB[r] = *(const uint4*)&g_bh[d * KSL + kc * 8];
        }

        for (int c = 0; c < 16; c++) {
            // ---- features for 1 q -> fp16 -> As2 ----
            {
                float a = ANG[(c * 8 + ql) * 33 + row];
                // Cody-Waite reduction mod 2*pi (C1=6.28125: 9 mantissa bits)
                float n = rintf(a * 0.15915494309189535f);
                float rr = fmaf(n, -6.28125f, a);
                rr = fmaf(n, -1.9353071795864769e-3f, rr);
                float s1, c1;
                __sincosf(rr, &s1, &c1);
                float f[12];
                f[0] = s1; f[1] = c1;
                float sk = s1, ck = c1;
                #pragma unroll
                for (int h = 1; h < KF; h++) {
                    float sn = fmaf(sk, c1, ck * s1);
                    float cn = fmaf(ck, c1, -sk * s1);
                    f[2 * h] = sn; f[2 * h + 1] = cn;
                    sk = sn; ck = cn;
                }
                uint32_t hv[6];
                #pragma unroll
                for (int g = 0; g < 6; g++) {
                    __half2 h2 = __floats2half2_rn(f[2 * g], f[2 * g + 1]);
                    hv[g] = *(uint32_t*)&h2;
                }
                uint64_t* dst = (uint64_t*)&As2[row * KP2 + ql * 12];
                dst[0] = (uint64_t)hv[0] | ((uint64_t)hv[1] << 32);
                dst[1] = (uint64_t)hv[2] | ((uint64_t)hv[3] << 32);
                dst[2] = (uint64_t)hv[4] | ((uint64_t)hv[5] << 32);
            }
            // ---- stage B chunk ----
            #pragma unroll
            for (int r = 0; r < 3; r++) {
                int idx = tid + 256 * r;
                int d   = idx / 12;
                int kc  = idx - d * 12;
                *(uint4*)&Bs2[d * KP2 + kc * 8] = nB[r];
            }
            __syncthreads();

            // ---- prefetch next B chunk ----
            if (c < 15) {
                #pragma unroll
                for (int r = 0; r < 3; r++) {
                    int idx = tid + 256 * r;
                    int d   = idx / 12;
                    int kc  = idx - d * 12;
                    nB[r] = *(const uint4*)&g_bh[d * KSL + (c + 1) * 96 + kc * 8];
                }
            }

            // ---- MMA: 6 ktiles x 2n ----
            #pragma unroll
            for (int kt = 0; kt < 6; kt++) {
                int k0 = kt * 16 + cc;
                int mr = wr2 * 16 + ra;
                uint32_t Af[4];
                Af[0] = *(const uint32_t*)&As2[mr * KP2 + k0];
                Af[1] = *(const uint32_t*)&As2[(mr + 8) * KP2 + k0];
                Af[2] = *(const uint32_t*)&As2[mr * KP2 + k0 + 8];
                Af[3] = *(const uint32_t*)&As2[(mr + 8) * KP2 + k0 + 8];
                #pragma unroll
                for (int nt = 0; nt < 2; nt++) {
                    int d0 = wd * 16 + nt * 8 + ra;
                    uint32_t Bf[2];
                    Bf[0] = *(const uint32_t*)&Bs2[d0 * KP2 + k0];
                    Bf[1] = *(const uint32_t*)&Bs2[d0 * KP2 + k0 + 8];
                    mma16816(acc[nt], Af, Bf);
                }
            }
            __syncthreads();
        }

        // ---- output epilogue ----
        int orow = r0 + wr2 * 16 + ra;
        #pragma unroll
        for (int nt = 0; nt < 2; nt++) {
            int ccg = wd * 16 + nt * 8 + cc;
            *(float2*)&out[orow * DOUT + ccg]       = make_float2(acc[nt][0], acc[nt][1]);
            *(float2*)&out[(orow + 8) * DOUT + ccg] = make_float2(acc[nt][2], acc[nt][3]);
        }
    }
}

// ---------------------------------------------------------------------------
extern "C" void kernel_launch(void* const* d_in, const int* in_sizes, int n_in,
                              void* d_out, int out_size) {
    const float* X0   = (const float*)d_in[0];
    const float* tvec = (const float*)d_in[1];
    const float* Wc_w = (const float*)d_in[2];
    const float* Wc_b = (const float*)d_in[3];
    const float* wvec = (const float*)d_in[4];
    const float* A    = (const float*)d_in[5];
    const float* Bp   = (const float*)d_in[6];
    float* out = (float*)d_out;

    prep_kernel<<<96, 256>>>(A, Bp, Wc_w);
    mega_kernel<<<ROWS / 32, 256>>>(X0, Wc_b, wvec, tvec, out);
}